// round 1
// baseline (speedup 1.0000x reference)
#include <cuda_runtime.h>
#include <cuda_bf16.h>

#define NPTS 2048
#define TPB  128
#define TILES (NPTS / TPB)   // 16
#define KNN  16
#define NB   8

// Scratch: per-block partial sums of mean-of-16-NN distances.
// Layout: [tensor(2)][batch(8)][tile(16)]
__device__ float g_part[2 * NB * TILES];

__global__ void __launch_bounds__(TPB, 8)
knn_kernel(const float* __restrict__ seed, const float* __restrict__ gt)
{
    __shared__ float sm[NPTS * 3];
    __shared__ float warp_sums[TPB / 32];

    const int tile = blockIdx.x;
    const int b    = blockIdx.y;
    const int z    = blockIdx.z;   // 0 = seed, 1 = gt_s

    const float* pts = (z == 0 ? seed : gt) + (size_t)b * NPTS * 3;

    // Cooperative load of the full batch into shared memory (24 KB)
    for (int idx = threadIdx.x; idx < NPTS * 3; idx += TPB)
        sm[idx] = pts[idx];
    __syncthreads();

    const int i = tile * TPB + threadIdx.x;
    const float xi = sm[3 * i + 0];
    const float yi = sm[3 * i + 1];
    const float zi = sm[3 * i + 2];

    // Running 16-smallest squared distances (register-resident, fully unrolled)
    float best[KNN];
#pragma unroll
    for (int t = 0; t < KNN; t++) best[t] = 3.4e38f;
    float worst = 3.4e38f;

    for (int j = 0; j < NPTS; j++) {
        // Broadcast reads: all lanes hit the same address -> no bank conflict
        const float dx = sm[3 * j + 0] - xi;
        const float dy = sm[3 * j + 1] - yi;
        const float dz = sm[3 * j + 2] - zi;
        const float d  = fmaf(dx, dx, fmaf(dy, dy, dz * dz));

        if (d < worst) {
            // Replace first occurrence of the current worst, then rescan for new worst
            bool done = false;
#pragma unroll
            for (int t = 0; t < KNN; t++) {
                if (!done && best[t] == worst) { best[t] = d; done = true; }
            }
            float w = -3.4e38f;
#pragma unroll
            for (int t = 0; t < KNN; t++) w = fmaxf(w, best[t]);
            worst = w;
        }
    }

    // mean of the 16 smallest for this point
    float s = 0.0f;
#pragma unroll
    for (int t = 0; t < KNN; t++) s += best[t];
    s *= (1.0f / KNN);

    // Deterministic in-block reduction: warp shuffles, then fixed-order smem sum
#pragma unroll
    for (int off = 16; off > 0; off >>= 1)
        s += __shfl_down_sync(0xffffffffu, s, off);

    const int wid = threadIdx.x >> 5;
    const int lid = threadIdx.x & 31;
    if (lid == 0) warp_sums[wid] = s;
    __syncthreads();

    if (threadIdx.x == 0) {
        float acc = 0.0f;
#pragma unroll
        for (int w = 0; w < TPB / 32; w++) acc += warp_sums[w];
        g_part[(z * NB + b) * TILES + tile] = acc;
    }
}

__global__ void finalize_kernel(float* __restrict__ out)
{
    const int lane = threadIdx.x;
    float val = 0.0f;
    if (lane < NB) {
        float S = 0.0f, G = 0.0f;
#pragma unroll
        for (int t = 0; t < TILES; t++) {
            S += g_part[(0 * NB + lane) * TILES + t];
            G += g_part[(1 * NB + lane) * TILES + t];
        }
        const float d = (S - G) * (1.0f / (float)NPTS);
        val = d * d;
    }
    // reduce the 8 lane values (lanes >= 8 hold 0)
#pragma unroll
    for (int off = 4; off > 0; off >>= 1)
        val += __shfl_down_sync(0xffffffffu, val, off);
    if (lane == 0)
        out[0] = val * (1.0f / (float)NB);
}

extern "C" void kernel_launch(void* const* d_in, const int* in_sizes, int n_in,
                              void* d_out, int out_size)
{
    const float* seed = (const float*)d_in[0];
    const float* gt_s = (const float*)d_in[1];
    float* out = (float*)d_out;

    dim3 grid(TILES, NB, 2);
    knn_kernel<<<grid, TPB>>>(seed, gt_s);
    finalize_kernel<<<1, 32>>>(out);
}

// round 2
// speedup vs baseline: 4.8496x; 4.8496x over previous
#include <cuda_runtime.h>
#include <cuda_bf16.h>

#define NPTS 2048
#define TPB  256
#define TILES (NPTS / TPB)   // 8
#define KNN  16
#define NB   8

// Scratch: per-block partial sums. Layout: [tensor(2)][batch(8)][tile(8)]
__device__ float g_part[2 * NB * TILES];

__global__ void __launch_bounds__(TPB, 1)
knn_kernel(const float* __restrict__ seed, const float* __restrict__ gt)
{
    __shared__ float4 sm[NPTS];           // (x, y, z, |p|^2)  = 32 KB
    __shared__ float warp_sums[TPB / 32];

    const int tile = blockIdx.x;
    const int b    = blockIdx.y;
    const int z    = blockIdx.z;   // 0 = seed, 1 = gt_s

    const float* pts = (z == 0 ? seed : gt) + (size_t)b * NPTS * 3;

    // Cooperative load: each thread packs 8 points into float4 (xyz + squared norm)
    for (int j = threadIdx.x; j < NPTS; j += TPB) {
        const float x = pts[3 * j + 0];
        const float y = pts[3 * j + 1];
        const float zc = pts[3 * j + 2];
        sm[j] = make_float4(x, y, zc, fmaf(x, x, fmaf(y, y, zc * zc)));
    }
    __syncthreads();

    const int i = tile * TPB + threadIdx.x;
    const float4 p = sm[i];
    const float si   = p.w;
    const float m2x  = -2.0f * p.x;
    const float m2y  = -2.0f * p.y;
    const float m2z  = -2.0f * p.z;

    // Sorted ascending top-16 smallest squared distances (register resident)
    float best[KNN];
#pragma unroll
    for (int t = 0; t < KNN; t++) best[t] = 3.4e38f;

#pragma unroll 4
    for (int j = 0; j < NPTS; j++) {
        const float4 q = sm[j];   // LDS.128 broadcast, conflict-free
        // d = |pi|^2 + |pj|^2 - 2 pi.pj  (matches reference formula)
        const float d = fmaf(q.x, m2x, fmaf(q.y, m2y, fmaf(q.z, m2z, si + q.w)));

        if (d < best[KNN - 1]) {
            // Parallel sorted insert: every slot reads only OLD values -> depth 2
#pragma unroll
            for (int t = KNN - 1; t >= 1; t--)
                best[t] = fminf(fmaxf(d, best[t - 1]), best[t]);
            best[0] = fminf(best[0], d);
        }
    }

    // mean of the 16 smallest for this point (tree sum)
    float s = 0.0f;
#pragma unroll
    for (int t = 0; t < KNN; t++) s += best[t];
    s *= (1.0f / KNN);

    // Deterministic in-block reduction
#pragma unroll
    for (int off = 16; off > 0; off >>= 1)
        s += __shfl_down_sync(0xffffffffu, s, off);

    const int wid = threadIdx.x >> 5;
    const int lid = threadIdx.x & 31;
    if (lid == 0) warp_sums[wid] = s;
    __syncthreads();

    if (threadIdx.x == 0) {
        float acc = 0.0f;
#pragma unroll
        for (int w = 0; w < TPB / 32; w++) acc += warp_sums[w];
        g_part[(z * NB + b) * TILES + tile] = acc;
    }
}

__global__ void finalize_kernel(float* __restrict__ out)
{
    const int lane = threadIdx.x;
    float val = 0.0f;
    if (lane < NB) {
        float S = 0.0f, G = 0.0f;
#pragma unroll
        for (int t = 0; t < TILES; t++) {
            S += g_part[(0 * NB + lane) * TILES + t];
            G += g_part[(1 * NB + lane) * TILES + t];
        }
        const float d = (S - G) * (1.0f / (float)NPTS);
        val = d * d;
    }
#pragma unroll
    for (int off = 4; off > 0; off >>= 1)
        val += __shfl_down_sync(0xffffffffu, val, off);
    if (lane == 0)
        out[0] = val * (1.0f / (float)NB);
}

extern "C" void kernel_launch(void* const* d_in, const int* in_sizes, int n_in,
                              void* d_out, int out_size)
{
    const float* seed = (const float*)d_in[0];
    const float* gt_s = (const float*)d_in[1];
    float* out = (float*)d_out;

    dim3 grid(TILES, NB, 2);
    knn_kernel<<<grid, TPB>>>(seed, gt_s);
    finalize_kernel<<<1, 32>>>(out);
}

// round 4
// speedup vs baseline: 8.4316x; 1.7386x over previous
#include <cuda_runtime.h>
#include <cuda_bf16.h>

#define NPTS 2048
#define TPB  256
#define TILES (NPTS / TPB)   // 8
#define KNN  16
#define NB   8
#define G    8               // candidates per branchless merge step

// Scratch: per-block partial sums. Layout: [tensor(2)][batch(8)][tile(8)]
__device__ float g_part[2 * NB * TILES];

// compare-exchange: a=min, b=max
#define CE(a, b) { float _lo = fminf(a, b); float _hi = fmaxf(a, b); a = _lo; b = _hi; }

__global__ void __launch_bounds__(TPB, 1)
knn_kernel(const float* __restrict__ seed, const float* __restrict__ gt)
{
    __shared__ float4 sm[NPTS];           // (x, y, z, |p|^2)  = 32 KB
    __shared__ float warp_sums[TPB / 32];

    const int tile = blockIdx.x;
    const int b    = blockIdx.y;
    const int z    = blockIdx.z;   // 0 = seed, 1 = gt_s

    const float* pts = (z == 0 ? seed : gt) + (size_t)b * NPTS * 3;

    for (int j = threadIdx.x; j < NPTS; j += TPB) {
        const float x  = pts[3 * j + 0];
        const float y  = pts[3 * j + 1];
        const float zc = pts[3 * j + 2];
        sm[j] = make_float4(x, y, zc, fmaf(x, x, fmaf(y, y, zc * zc)));
    }
    __syncthreads();

    const int i = tile * TPB + threadIdx.x;
    const float4 p = sm[i];
    const float si  = p.w;
    const float m2x = -2.0f * p.x;
    const float m2y = -2.0f * p.y;
    const float m2z = -2.0f * p.z;

    // best[0..15] ascending, register resident
    float best[KNN];
#pragma unroll
    for (int t = 0; t < KNN; t++) best[t] = 3.4e38f;

#pragma unroll 1
    for (int g = 0; g < NPTS; g += G) {
        // --- 8 distances (fma pipe) ---
        float c[G];
#pragma unroll
        for (int u = 0; u < G; u++) {
            const float4 q = sm[g + u];   // LDS.128 broadcast, conflict-free
            c[u] = fmaf(q.x, m2x, fmaf(q.y, m2y, fmaf(q.z, m2z, si + q.w)));
        }

        // --- sort8 ascending: Batcher odd-even mergesort, 19 CE ---
        CE(c[0], c[1]); CE(c[2], c[3]); CE(c[4], c[5]); CE(c[6], c[7]);
        CE(c[0], c[2]); CE(c[1], c[3]); CE(c[4], c[6]); CE(c[5], c[7]);
        CE(c[1], c[2]); CE(c[5], c[6]);
        CE(c[0], c[4]); CE(c[1], c[5]); CE(c[2], c[6]); CE(c[3], c[7]);
        CE(c[2], c[4]); CE(c[3], c[5]);
        CE(c[1], c[2]); CE(c[3], c[4]); CE(c[5], c[6]);

        // --- half-cleaner: pair best tail (desc) with candidates (asc) ---
        // Exact 16-smallest multiset of the 24 values; best[] becomes bitonic.
        best[15] = fminf(best[15], c[0]);
        best[14] = fminf(best[14], c[1]);
        best[13] = fminf(best[13], c[2]);
        best[12] = fminf(best[12], c[3]);
        best[11] = fminf(best[11], c[4]);
        best[10] = fminf(best[10], c[5]);
        best[9]  = fminf(best[9],  c[6]);
        best[8]  = fminf(best[8],  c[7]);

        // --- bitonic merge16 ascending: 32 CE ---
#pragma unroll
        for (int t = 0; t < 8; t++)  CE(best[t], best[t + 8]);
#pragma unroll
        for (int h = 0; h < 16; h += 8)
#pragma unroll
            for (int t = 0; t < 4; t++) CE(best[h + t], best[h + t + 4]);
#pragma unroll
        for (int h = 0; h < 16; h += 4)
#pragma unroll
            for (int t = 0; t < 2; t++) CE(best[h + t], best[h + t + 2]);
#pragma unroll
        for (int h = 0; h < 16; h += 2)
            CE(best[h], best[h + 1]);
    }

    // mean of the 16 smallest for this point
    float s = 0.0f;
#pragma unroll
    for (int t = 0; t < KNN; t++) s += best[t];
    s *= (1.0f / KNN);

    // Deterministic in-block reduction
#pragma unroll
    for (int off = 16; off > 0; off >>= 1)
        s += __shfl_down_sync(0xffffffffu, s, off);

    const int wid = threadIdx.x >> 5;
    const int lid = threadIdx.x & 31;
    if (lid == 0) warp_sums[wid] = s;
    __syncthreads();

    if (threadIdx.x == 0) {
        float acc = 0.0f;
#pragma unroll
        for (int w = 0; w < TPB / 32; w++) acc += warp_sums[w];
        g_part[(z * NB + b) * TILES + tile] = acc;
    }
}

__global__ void finalize_kernel(float* __restrict__ out)
{
    const int lane = threadIdx.x;
    float val = 0.0f;
    if (lane < NB) {
        float S = 0.0f, Gv = 0.0f;
#pragma unroll
        for (int t = 0; t < TILES; t++) {
            S  += g_part[(0 * NB + lane) * TILES + t];
            Gv += g_part[(1 * NB + lane) * TILES + t];
        }
        const float d = (S - Gv) * (1.0f / (float)NPTS);
        val = d * d;
    }
#pragma unroll
    for (int off = 4; off > 0; off >>= 1)
        val += __shfl_down_sync(0xffffffffu, val, off);
    if (lane == 0)
        out[0] = val * (1.0f / (float)NB);
}

extern "C" void kernel_launch(void* const* d_in, const int* in_sizes, int n_in,
                              void* d_out, int out_size)
{
    const float* seed = (const float*)d_in[0];
    const float* gt_s = (const float*)d_in[1];
    float* out = (float*)d_out;

    dim3 grid(TILES, NB, 2);
    knn_kernel<<<grid, TPB>>>(seed, gt_s);
    finalize_kernel<<<1, 32>>>(out);
}

// round 6
// speedup vs baseline: 8.4912x; 1.0071x over previous
#include <cuda_runtime.h>
#include <cuda_bf16.h>

#define NPTS 2048
#define TPB  256
#define TILES (NPTS / TPB)   // 8
#define KNN  16
#define NB   8
#define G    8
#define NGROUPS (NPTS / G)   // 256
#define STPB 512             // sort kernel threads

// Scratch: per-block partial sums. Layout: [tensor(2)][batch(8)][tile(8)]
__device__ float g_part[2 * NB * TILES];
// Morton-sorted points with |p|^2 in .w : [tensor(2)][batch(8)][2048]
__device__ float4 g_sorted[2 * NB * NPTS];

// compare-exchange: a=min, b=max
#define CE(a, b) { float _lo = fminf(a, b); float _hi = fmaxf(a, b); a = _lo; b = _hi; }

__device__ __forceinline__ unsigned expand3(unsigned v) {
    // spread 10(7) bits so there are 2 zero bits between each
    v &= 0x3FFu;
    v = (v | (v << 16)) & 0x030000FFu;
    v = (v | (v << 8))  & 0x0300F00Fu;
    v = (v | (v << 4))  & 0x030C30C3u;
    v = (v | (v << 2))  & 0x09249249u;
    return v;
}

__global__ void __launch_bounds__(STPB, 1)
sort_kernel(const float* __restrict__ seed, const float* __restrict__ gt)
{
    __shared__ unsigned keys[NPTS];
    __shared__ float4 spts[NPTS];

    const int b = blockIdx.x;
    const int z = blockIdx.y;
    const float* pts = (z == 0 ? seed : gt) + (size_t)b * NPTS * 3;
    const int tid = threadIdx.x;

    for (int j = tid; j < NPTS; j += STPB) {
        const float x  = pts[3 * j + 0];
        const float y  = pts[3 * j + 1];
        const float zc = pts[3 * j + 2];
        spts[j] = make_float4(x, y, zc, fmaf(x, x, fmaf(y, y, zc * zc)));
        // 7-bit quantization per axis over [-4, 4]
        const unsigned qx = (unsigned)fminf(fmaxf((x  + 4.0f) * 16.0f, 0.0f), 127.0f);
        const unsigned qy = (unsigned)fminf(fmaxf((y  + 4.0f) * 16.0f, 0.0f), 127.0f);
        const unsigned qz = (unsigned)fminf(fmaxf((zc + 4.0f) * 16.0f, 0.0f), 127.0f);
        const unsigned code = (expand3(qx) << 2) | (expand3(qy) << 1) | expand3(qz); // 21 bits
        keys[j] = (code << 11) | (unsigned)j;   // unique keys -> deterministic order
    }
    __syncthreads();

    // Bitonic sort of 2048 unique uint32 keys
    for (unsigned k = 2; k <= NPTS; k <<= 1) {
        for (unsigned jj = k >> 1; jj > 0; jj >>= 1) {
            for (int idx = tid; idx < NPTS; idx += STPB) {
                const int partner = idx ^ (int)jj;
                if (partner > idx) {
                    const bool up = ((idx & k) == 0);
                    const unsigned a = keys[idx];
                    const unsigned c = keys[partner];
                    if ((a > c) == up) { keys[idx] = c; keys[partner] = a; }
                }
            }
            __syncthreads();
        }
    }

    float4* dst = g_sorted + (size_t)(z * NB + b) * NPTS;
    for (int idx = tid; idx < NPTS; idx += STPB)
        dst[idx] = spts[keys[idx] & 2047u];
}

__global__ void __launch_bounds__(TPB, 1)
knn_kernel()
{
    __shared__ float4 sm[NPTS];           // 32 KB
    __shared__ float warp_sums[TPB / 32];

    const int tile = blockIdx.x;
    const int b    = blockIdx.y;
    const int z    = blockIdx.z;

    const float4* src = g_sorted + (size_t)(z * NB + b) * NPTS;
    for (int j = threadIdx.x; j < NPTS; j += TPB)
        sm[j] = src[j];
    __syncthreads();

    const int i = tile * TPB + threadIdx.x;
    const float4 p = sm[i];
    const float si  = p.w;
    const float m2x = -2.0f * p.x;
    const float m2y = -2.0f * p.y;
    const float m2z = -2.0f * p.z;

    float best[KNN];
#pragma unroll
    for (int t = 0; t < KNN; t++) best[t] = 3.4e38f;

    // Start the scan at this warp's own Morton neighborhood so best[15]
    // tightens immediately; then most far groups fail the vote and skip.
    const int warp = threadIdx.x >> 5;
    const int g0 = (tile * TPB + warp * 32) >> 3;

#pragma unroll 1
    for (int gg = 0; gg < NGROUPS; gg++) {
        const int base = ((g0 + gg) & (NGROUPS - 1)) << 3;

        float c[G];
#pragma unroll
        for (int u = 0; u < G; u++) {
            const float4 q = sm[base + u];   // LDS.128 broadcast
            c[u] = fmaf(q.x, m2x, fmaf(q.y, m2y, fmaf(q.z, m2z, si + q.w)));
        }

        // group min (7 ops) + warp vote: skip merge if nobody can improve
        const float m01 = fminf(c[0], c[1]);
        const float m23 = fminf(c[2], c[3]);
        const float m45 = fminf(c[4], c[5]);
        const float m67 = fminf(c[6], c[7]);
        const float m   = fminf(fminf(m01, m23), fminf(m45, m67));

        if (__any_sync(0xffffffffu, m < best[KNN - 1])) {
            // --- sort8 ascending: Batcher odd-even mergesort, 19 CE ---
            CE(c[0], c[1]); CE(c[2], c[3]); CE(c[4], c[5]); CE(c[6], c[7]);
            CE(c[0], c[2]); CE(c[1], c[3]); CE(c[4], c[6]); CE(c[5], c[7]);
            CE(c[1], c[2]); CE(c[5], c[6]);
            CE(c[0], c[4]); CE(c[1], c[5]); CE(c[2], c[6]); CE(c[3], c[7]);
            CE(c[2], c[4]); CE(c[3], c[5]);
            CE(c[1], c[2]); CE(c[3], c[4]); CE(c[5], c[6]);

            // --- half-cleaner with best tail ---
            best[15] = fminf(best[15], c[0]);
            best[14] = fminf(best[14], c[1]);
            best[13] = fminf(best[13], c[2]);
            best[12] = fminf(best[12], c[3]);
            best[11] = fminf(best[11], c[4]);
            best[10] = fminf(best[10], c[5]);
            best[9]  = fminf(best[9],  c[6]);
            best[8]  = fminf(best[8],  c[7]);

            // --- bitonic merge16 ascending: 32 CE ---
#pragma unroll
            for (int t = 0; t < 8; t++)  CE(best[t], best[t + 8]);
#pragma unroll
            for (int h = 0; h < 16; h += 8)
#pragma unroll
                for (int t = 0; t < 4; t++) CE(best[h + t], best[h + t + 4]);
#pragma unroll
            for (int h = 0; h < 16; h += 4)
#pragma unroll
                for (int t = 0; t < 2; t++) CE(best[h + t], best[h + t + 2]);
#pragma unroll
            for (int h = 0; h < 16; h += 2)
                CE(best[h], best[h + 1]);
        }
    }

    float s = 0.0f;
#pragma unroll
    for (int t = 0; t < KNN; t++) s += best[t];
    s *= (1.0f / KNN);

#pragma unroll
    for (int off = 16; off > 0; off >>= 1)
        s += __shfl_down_sync(0xffffffffu, s, off);

    const int lid = threadIdx.x & 31;
    if (lid == 0) warp_sums[warp] = s;
    __syncthreads();

    if (threadIdx.x == 0) {
        float acc = 0.0f;
#pragma unroll
        for (int w = 0; w < TPB / 32; w++) acc += warp_sums[w];
        g_part[(z * NB + b) * TILES + tile] = acc;
    }
}

__global__ void finalize_kernel(float* __restrict__ out)
{
    const int lane = threadIdx.x;
    float val = 0.0f;
    if (lane < NB) {
        float S = 0.0f, Gv = 0.0f;
#pragma unroll
        for (int t = 0; t < TILES; t++) {
            S  += g_part[(0 * NB + lane) * TILES + t];
            Gv += g_part[(1 * NB + lane) * TILES + t];
        }
        const float d = (S - Gv) * (1.0f / (float)NPTS);
        val = d * d;
    }
#pragma unroll
    for (int off = 4; off > 0; off >>= 1)
        val += __shfl_down_sync(0xffffffffu, val, off);
    if (lane == 0)
        out[0] = val * (1.0f / (float)NB);
}

extern "C" void kernel_launch(void* const* d_in, const int* in_sizes, int n_in,
                              void* d_out, int out_size)
{
    const float* seed = (const float*)d_in[0];
    const float* gt_s = (const float*)d_in[1];
    float* out = (float*)d_out;

    dim3 sgrid(NB, 2);
    sort_kernel<<<sgrid, STPB>>>(seed, gt_s);

    dim3 grid(TILES, NB, 2);
    knn_kernel<<<grid, TPB>>>();
    finalize_kernel<<<1, 32>>>(out);
}

// round 7
// speedup vs baseline: 9.8940x; 1.1652x over previous
#include <cuda_runtime.h>
#include <cuda_bf16.h>

#define NPTS 2048
#define TPB  256
#define TILES (NPTS / TPB)   // 8
#define KNN  16
#define NB   8
#define G    8
#define NGROUPS (NPTS / G)   // 256
#define STPB 1024            // sort kernel threads
#define NBLOCKS (TILES * NB * 2)   // 128

// Scratch: per-block partial sums. Layout: [tensor(2)][batch(8)][tile(8)]
__device__ float g_part[2 * NB * TILES];
// Morton-sorted points with |p|^2 in .w : [tensor(2)][batch(8)][2048]
__device__ float4 g_sorted[2 * NB * NPTS];
__device__ unsigned g_cnt;   // last-block ticket; self-resets each launch

// compare-exchange: a=min, b=max
#define CE(a, b) { float _lo = fminf(a, b); float _hi = fmaxf(a, b); a = _lo; b = _hi; }

__device__ __forceinline__ unsigned expand3(unsigned v) {
    v &= 0x3FFu;
    v = (v | (v << 16)) & 0x030000FFu;
    v = (v | (v << 8))  & 0x0300F00Fu;
    v = (v | (v << 4))  & 0x030C30C3u;
    v = (v | (v << 2))  & 0x09249249u;
    return v;
}

__global__ void __launch_bounds__(STPB, 1)
sort_kernel(const float* __restrict__ seed, const float* __restrict__ gt)
{
    __shared__ unsigned keys[NPTS];
    __shared__ float4 spts[NPTS];

    const int b = blockIdx.x;
    const int z = blockIdx.y;
    const float* pts = (z == 0 ? seed : gt) + (size_t)b * NPTS * 3;
    const int tid = threadIdx.x;

#pragma unroll
    for (int j = tid; j < NPTS; j += STPB) {
        const float x  = pts[3 * j + 0];
        const float y  = pts[3 * j + 1];
        const float zc = pts[3 * j + 2];
        spts[j] = make_float4(x, y, zc, fmaf(x, x, fmaf(y, y, zc * zc)));
        const unsigned qx = (unsigned)fminf(fmaxf((x  + 4.0f) * 16.0f, 0.0f), 127.0f);
        const unsigned qy = (unsigned)fminf(fmaxf((y  + 4.0f) * 16.0f, 0.0f), 127.0f);
        const unsigned qz = (unsigned)fminf(fmaxf((zc + 4.0f) * 16.0f, 0.0f), 127.0f);
        const unsigned code = (expand3(qx) << 2) | (expand3(qy) << 1) | expand3(qz);
        keys[j] = (code << 11) | (unsigned)j;   // unique keys -> deterministic order
    }
    __syncthreads();

    // Bitonic sort, exactly one compare-exchange per thread per phase
    for (unsigned k = 2; k <= NPTS; k <<= 1) {
        for (unsigned jj = k >> 1; jj > 0; jj >>= 1) {
            const unsigned t = (unsigned)tid;
            const unsigned i = ((t & ~(jj - 1u)) << 1) | (t & (jj - 1u));
            const unsigned p = i | jj;
            const bool up = ((i & k) == 0u);
            const unsigned a  = keys[i];
            const unsigned c  = keys[p];
            const unsigned lo = a < c ? a : c;
            const unsigned hi = a < c ? c : a;
            keys[i] = up ? lo : hi;
            keys[p] = up ? hi : lo;
            __syncthreads();
        }
    }

    float4* dst = g_sorted + (size_t)(z * NB + b) * NPTS;
#pragma unroll
    for (int idx = tid; idx < NPTS; idx += STPB)
        dst[idx] = spts[keys[idx] & 2047u];
}

__global__ void __launch_bounds__(TPB, 1)
knn_kernel(float* __restrict__ out)
{
    __shared__ float4 sm[NPTS];           // 32 KB
    __shared__ float warp_sums[TPB / 32];
    __shared__ unsigned s_ticket;

    const int tile = blockIdx.x;
    const int b    = blockIdx.y;
    const int z    = blockIdx.z;

    const float4* src = g_sorted + (size_t)(z * NB + b) * NPTS;
    for (int j = threadIdx.x; j < NPTS; j += TPB)
        sm[j] = src[j];
    __syncthreads();

    const int i = tile * TPB + threadIdx.x;
    const float4 p = sm[i];
    const float si  = p.w;
    const float m2x = -2.0f * p.x;
    const float m2y = -2.0f * p.y;
    const float m2z = -2.0f * p.z;

    float best[KNN];
#pragma unroll
    for (int t = 0; t < KNN; t++) best[t] = 3.4e38f;

    const int warp = threadIdx.x >> 5;
    const int g0 = (tile * TPB + warp * 32) >> 3;

#pragma unroll 1
    for (int gg = 0; gg < NGROUPS; gg++) {
        const int base = ((g0 + gg) & (NGROUPS - 1)) << 3;

        float c[G];
#pragma unroll
        for (int u = 0; u < G; u++) {
            const float4 q = sm[base + u];   // LDS.128 broadcast
            c[u] = fmaf(q.x, m2x, fmaf(q.y, m2y, fmaf(q.z, m2z, si + q.w)));
        }

        const float m01 = fminf(c[0], c[1]);
        const float m23 = fminf(c[2], c[3]);
        const float m45 = fminf(c[4], c[5]);
        const float m67 = fminf(c[6], c[7]);
        const float m   = fminf(fminf(m01, m23), fminf(m45, m67));

        if (__any_sync(0xffffffffu, m < best[KNN - 1])) {
            // sort8 ascending (Batcher, 19 CE)
            CE(c[0], c[1]); CE(c[2], c[3]); CE(c[4], c[5]); CE(c[6], c[7]);
            CE(c[0], c[2]); CE(c[1], c[3]); CE(c[4], c[6]); CE(c[5], c[7]);
            CE(c[1], c[2]); CE(c[5], c[6]);
            CE(c[0], c[4]); CE(c[1], c[5]); CE(c[2], c[6]); CE(c[3], c[7]);
            CE(c[2], c[4]); CE(c[3], c[5]);
            CE(c[1], c[2]); CE(c[3], c[4]); CE(c[5], c[6]);

            // half-cleaner with best tail
            best[15] = fminf(best[15], c[0]);
            best[14] = fminf(best[14], c[1]);
            best[13] = fminf(best[13], c[2]);
            best[12] = fminf(best[12], c[3]);
            best[11] = fminf(best[11], c[4]);
            best[10] = fminf(best[10], c[5]);
            best[9]  = fminf(best[9],  c[6]);
            best[8]  = fminf(best[8],  c[7]);

            // bitonic merge16 ascending (32 CE)
#pragma unroll
            for (int t = 0; t < 8; t++)  CE(best[t], best[t + 8]);
#pragma unroll
            for (int h = 0; h < 16; h += 8)
#pragma unroll
                for (int t = 0; t < 4; t++) CE(best[h + t], best[h + t + 4]);
#pragma unroll
            for (int h = 0; h < 16; h += 4)
#pragma unroll
                for (int t = 0; t < 2; t++) CE(best[h + t], best[h + t + 2]);
#pragma unroll
            for (int h = 0; h < 16; h += 2)
                CE(best[h], best[h + 1]);
        }
    }

    float s = 0.0f;
#pragma unroll
    for (int t = 0; t < KNN; t++) s += best[t];
    s *= (1.0f / KNN);

#pragma unroll
    for (int off = 16; off > 0; off >>= 1)
        s += __shfl_down_sync(0xffffffffu, s, off);

    const int lid = threadIdx.x & 31;
    if (lid == 0) warp_sums[warp] = s;
    __syncthreads();

    if (threadIdx.x == 0) {
        float acc = 0.0f;
#pragma unroll
        for (int w = 0; w < TPB / 32; w++) acc += warp_sums[w];
        g_part[(z * NB + b) * TILES + tile] = acc;
        __threadfence();
        s_ticket = atomicAdd(&g_cnt, 1u);
    }
    __syncthreads();

    // Last block to finish performs the (deterministic, fixed-order) finalize
    if (s_ticket == NBLOCKS - 1) {
        const int lane = threadIdx.x;
        if (lane < 32) {
            float val = 0.0f;
            if (lane < NB) {
                float S = 0.0f, Gv = 0.0f;
#pragma unroll
                for (int t = 0; t < TILES; t++) {
                    S  += g_part[(0 * NB + lane) * TILES + t];
                    Gv += g_part[(1 * NB + lane) * TILES + t];
                }
                const float d = (S - Gv) * (1.0f / (float)NPTS);
                val = d * d;
            }
#pragma unroll
            for (int off = 4; off > 0; off >>= 1)
                val += __shfl_down_sync(0xffffffffu, val, off);
            if (lane == 0) {
                out[0] = val * (1.0f / (float)NB);
                g_cnt = 0;   // self-reset for next launch / graph replay
            }
        }
    }
}

extern "C" void kernel_launch(void* const* d_in, const int* in_sizes, int n_in,
                              void* d_out, int out_size)
{
    const float* seed = (const float*)d_in[0];
    const float* gt_s = (const float*)d_in[1];
    float* out = (float*)d_out;

    dim3 sgrid(NB, 2);
    sort_kernel<<<sgrid, STPB>>>(seed, gt_s);

    dim3 grid(TILES, NB, 2);
    knn_kernel<<<grid, TPB>>>(out);
}